// round 8
// baseline (speedup 1.0000x reference)
#include <cuda_runtime.h>

// Shapes (fixed per reference): B=1024, C=200, L=3, DIM=512, SEQ=C+1=201
#define B_    1024
#define C_    200
#define DIM_  512
#define SEQ_  201
#define BT    8        // batch rows per block (full W reuse)
#define NS    3        // seq positions per block (201 = 67 * 3)
#define NCOL  (NS + 2) // x columns needed: [s0-2, s0+2] clamped

// out[b,0,d]   = cls[d] + pe[0,d]
// out[b,c+1,d] = x[b,clamp(c-1)]*W[c,0,d] + x[b,c]*W[c,1,d] + x[b,clamp(c+1)]*W[c,2,d] + pe[c+1,d]

__device__ __forceinline__ void stcs4(float4* p, float4 v) {
    // streaming store: evict-first in L2, drain straight to DRAM
    asm volatile("st.global.cs.v4.f32 [%0], {%1, %2, %3, %4};"
                 :: "l"(p), "f"(v.x), "f"(v.y), "f"(v.z), "f"(v.w) : "memory");
}

__global__ __launch_bounds__(128, 10)
void GSE_band_proj_kernel(const float* __restrict__ x,
                          const float* __restrict__ W,
                          const float* __restrict__ cls,
                          const float* __restrict__ pe,
                          float* __restrict__ out) {
    __shared__ float xs[NCOL][BT];           // 5 x-columns for 8 batch rows (160 B)

    const int d4     = threadIdx.x;          // 0..127 (float4 index into DIM=512)
    const int b_base = blockIdx.y * BT;
    const int s0     = blockIdx.x * NS;      // first of NS consecutive seq positions

    // Cooperative x-window fill: column j holds x[:, clamp(s0-2+j)].
    // For s = s0+js (c = s-1): cm1 -> col js, c -> col js+1, cp1 -> col js+2.
    if (threadIdx.x < NCOL * BT) {
        const int j = threadIdx.x / BT;
        const int i = threadIdx.x % BT;
        int col = s0 - 2 + j;
        col = (col < 0) ? 0 : (col > C_ - 1 ? C_ - 1 : col);
        xs[j][i] = __ldg(x + (size_t)(b_base + i) * C_ + col);
    }
    __syncthreads();

    #pragma unroll
    for (int js = 0; js < NS; js++) {
        const int s = s0 + js;               // 0..200

        if (s == 0) {
            const float4 cv = reinterpret_cast<const float4*>(cls)[d4];
            const float4 pv = reinterpret_cast<const float4*>(pe)[d4];
            float4 r;
            r.x = cv.x + pv.x;  r.y = cv.y + pv.y;
            r.z = cv.z + pv.z;  r.w = cv.w + pv.w;
            #pragma unroll
            for (int i = 0; i < BT; i++) {
                const size_t b = (size_t)(b_base + i);
                stcs4(reinterpret_cast<float4*>(out + (b * SEQ_) * DIM_) + d4, r);
            }
            continue;
        }

        const int c = s - 1;                 // 0..199

        // Per-(c,d4) constants, reused across BT batch rows (L2-resident broadcast).
        const float4 w0 = reinterpret_cast<const float4*>(W + ((size_t)c * 3 + 0) * DIM_)[d4];
        const float4 w1 = reinterpret_cast<const float4*>(W + ((size_t)c * 3 + 1) * DIM_)[d4];
        const float4 w2 = reinterpret_cast<const float4*>(W + ((size_t)c * 3 + 2) * DIM_)[d4];
        const float4 pv = reinterpret_cast<const float4*>(pe + (size_t)(c + 1) * DIM_)[d4];

        #pragma unroll
        for (int i = 0; i < BT; i++) {
            const float a = xs[js    ][i];   // broadcast LDS (warp-uniform)
            const float m = xs[js + 1][i];
            const float z = xs[js + 2][i];
            float4 r;
            r.x = fmaf(a, w0.x, fmaf(m, w1.x, fmaf(z, w2.x, pv.x)));
            r.y = fmaf(a, w0.y, fmaf(m, w1.y, fmaf(z, w2.y, pv.y)));
            r.z = fmaf(a, w0.z, fmaf(m, w1.z, fmaf(z, w2.z, pv.z)));
            r.w = fmaf(a, w0.w, fmaf(m, w1.w, fmaf(z, w2.w, pv.w)));
            const size_t b = (size_t)(b_base + i);
            stcs4(reinterpret_cast<float4*>(out + (b * SEQ_ + s) * DIM_) + d4, r);
        }
    }
}

extern "C" void kernel_launch(void* const* d_in, const int* in_sizes, int n_in,
                              void* d_out, int out_size) {
    const float* x   = (const float*)d_in[0];
    const float* W   = (const float*)d_in[1];
    const float* cls = (const float*)d_in[2];
    const float* pe  = (const float*)d_in[3];
    float* out = (float*)d_out;

    dim3 grid(SEQ_ / NS, B_ / BT, 1);   // 67 x 128 blocks = 8576 CTAs
    dim3 block(DIM_ / 4, 1, 1);         // 128 threads, one float4 each
    GSE_band_proj_kernel<<<grid, block>>>(x, W, cls, pe, out);
}

// round 9
// speedup vs baseline: 1.0140x; 1.0140x over previous
#include <cuda_runtime.h>

// Shapes (fixed per reference): B=1024, C=200, L=3, DIM=512, SEQ=C+1=201
#define B_    1024
#define C_    200
#define DIM_  512
#define SEQ_  201
#define BT    16       // batch rows per block (double W reuse; x lives in smem)

// out[b,0,d]   = cls[d] + pe[0,d]
// out[b,c+1,d] = x[b,clamp(c-1)]*W[c,0,d] + x[b,c]*W[c,1,d] + x[b,clamp(c+1)]*W[c,2,d] + pe[c+1,d]

__device__ __forceinline__ void stcs4(float4* p, float4 v) {
    // streaming store: evict-first in L2, drain straight to DRAM
    asm volatile("st.global.cs.v4.f32 [%0], {%1, %2, %3, %4};"
                 :: "l"(p), "f"(v.x), "f"(v.y), "f"(v.z), "f"(v.w) : "memory");
}

__global__ __launch_bounds__(128, 10)
void GSE_band_proj_kernel(const float* __restrict__ x,
                          const float* __restrict__ W,
                          const float* __restrict__ cls,
                          const float* __restrict__ pe,
                          float* __restrict__ out) {
    __shared__ float xs[3][BT];              // 3 x-columns for 16 batch rows (192 B)

    const int d4     = threadIdx.x;          // 0..127 (float4 index into DIM=512)
    const int s      = blockIdx.x;           // 0..200 (sequence position)
    const int b_base = blockIdx.y * BT;

    if (s == 0) {
        // cls row: batch-invariant value, pure store stream
        const float4 cv = reinterpret_cast<const float4*>(cls)[d4];
        const float4 pv = reinterpret_cast<const float4*>(pe)[d4];
        float4 r;
        r.x = cv.x + pv.x;  r.y = cv.y + pv.y;
        r.z = cv.z + pv.z;  r.w = cv.w + pv.w;
        #pragma unroll
        for (int i = 0; i < BT; i++) {
            const size_t b = (size_t)(b_base + i);
            stcs4(reinterpret_cast<float4*>(out + (b * SEQ_) * DIM_) + d4, r);
        }
        return;
    }

    const int c = s - 1;                     // 0..199

    // Cooperative x-window fill: col j in {0,1,2} = x[:, clamp(c-1+j)]
    if (threadIdx.x < 3 * BT) {
        const int j = threadIdx.x / BT;      // 0..2
        const int i = threadIdx.x % BT;      // 0..15
        int col = c - 1 + j;
        col = (col < 0) ? 0 : (col > C_ - 1 ? C_ - 1 : col);
        xs[j][i] = __ldg(x + (size_t)(b_base + i) * C_ + col);
    }

    // Per-(c,d4) constants, reused across BT=16 batch rows (L2-resident broadcast).
    const float4 w0 = reinterpret_cast<const float4*>(W + ((size_t)c * 3 + 0) * DIM_)[d4];
    const float4 w1 = reinterpret_cast<const float4*>(W + ((size_t)c * 3 + 1) * DIM_)[d4];
    const float4 w2 = reinterpret_cast<const float4*>(W + ((size_t)c * 3 + 2) * DIM_)[d4];
    const float4 pv = reinterpret_cast<const float4*>(pe + (size_t)(c + 1) * DIM_)[d4];

    __syncthreads();

    #pragma unroll
    for (int i = 0; i < BT; i++) {
        const float a = xs[0][i];            // broadcast LDS (warp-uniform)
        const float m = xs[1][i];
        const float z = xs[2][i];
        float4 r;
        r.x = fmaf(a, w0.x, fmaf(m, w1.x, fmaf(z, w2.x, pv.x)));
        r.y = fmaf(a, w0.y, fmaf(m, w1.y, fmaf(z, w2.y, pv.y)));
        r.z = fmaf(a, w0.z, fmaf(m, w1.z, fmaf(z, w2.z, pv.z)));
        r.w = fmaf(a, w0.w, fmaf(m, w1.w, fmaf(z, w2.w, pv.w)));
        const size_t b = (size_t)(b_base + i);
        stcs4(reinterpret_cast<float4*>(out + (b * SEQ_ + s) * DIM_) + d4, r);
    }
}

extern "C" void kernel_launch(void* const* d_in, const int* in_sizes, int n_in,
                              void* d_out, int out_size) {
    const float* x   = (const float*)d_in[0];
    const float* W   = (const float*)d_in[1];
    const float* cls = (const float*)d_in[2];
    const float* pe  = (const float*)d_in[3];
    float* out = (float*)d_out;

    dim3 grid(SEQ_, B_ / BT, 1);    // 201 x 64 blocks = 12864 CTAs
    dim3 block(DIM_ / 4, 1, 1);     // 128 threads, one float4 each
    GSE_band_proj_kernel<<<grid, block>>>(x, W, cls, pe, out);
}